// round 1
// baseline (speedup 1.0000x reference)
#include <cuda_runtime.h>

#define BATCH 4096
#define TSEQ  20
#define INSZ  512
#define HSZ   512
#define RNK   20
#define G4    2048   // 4*H
#define RV    40     // combined rank (u | hu)
#define NB    32     // batch rows per block in step kernel
#define WTS   132    // padded row stride for transposed whh_a tile in smem

// Scratch (no allocations allowed -> device globals)
__device__ float g_u[BATCH * TSEQ * RNK];     // [b][t][r]  input projection
__device__ float g_c[BATCH * HSZ];            // cell state
__device__ float g_hu[2][4 * BATCH * RNK];    // [parity][jtile][b][r] h@whh_a partials

// ---------------------------------------------------------------------------
__global__ void kInit() {
    const int n1 = BATCH * HSZ;
    const int n2 = 4 * BATCH * RNK;
    const int stride = gridDim.x * blockDim.x;
    for (int i = blockIdx.x * blockDim.x + threadIdx.x; i < n1; i += stride) g_c[i] = 0.f;
    for (int i = blockIdx.x * blockDim.x + threadIdx.x; i < n2; i += stride) g_hu[0][i] = 0.f;
}

// ---------------------------------------------------------------------------
// u[m][r] = sum_k x[m][k] * wih_a[k][r],  m = b*T + t  (81920 rows)
__global__ __launch_bounds__(256) void kPre(const float* __restrict__ x,
                                            const float* __restrict__ wa) {
    __shared__ __align__(16) float was[INSZ * RNK];   // [k][r], 40KB
    for (int idx = threadIdx.x; idx < INSZ * RNK; idx += blockDim.x) was[idx] = wa[idx];
    __syncthreads();

    const int row = blockIdx.x * blockDim.x + threadIdx.x;   // exact: 320*256 = 81920
    const float4* xr = reinterpret_cast<const float4*>(x + (long)row * INSZ);

    float acc[RNK];
#pragma unroll
    for (int r = 0; r < RNK; r++) acc[r] = 0.f;

#pragma unroll 4
    for (int k4 = 0; k4 < INSZ / 4; k4++) {
        float4 xv = xr[k4];
#pragma unroll
        for (int i = 0; i < 4; i++) {
            float kv = (i == 0) ? xv.x : (i == 1) ? xv.y : (i == 2) ? xv.z : xv.w;
            const float4* w4 = reinterpret_cast<const float4*>(was + (k4 * 4 + i) * RNK);
#pragma unroll
            for (int q = 0; q < 5; q++) {
                float4 w = w4[q];
                acc[4*q+0] = fmaf(kv, w.x, acc[4*q+0]);
                acc[4*q+1] = fmaf(kv, w.y, acc[4*q+1]);
                acc[4*q+2] = fmaf(kv, w.z, acc[4*q+2]);
                acc[4*q+3] = fmaf(kv, w.w, acc[4*q+3]);
            }
        }
    }
    float* up = g_u + (long)row * RNK;
#pragma unroll
    for (int r = 0; r < RNK; r++) up[r] = acc[r];
}

// ---------------------------------------------------------------------------
// One LSTM timestep. Grid (4 jtiles, 128 bchunks), block 512.
// thread = (gate = tid>>7, jj = tid&127); holds 40 gate weights in registers.
// Also produces the h@whh_a partials for the NEXT step (fused, no extra kernel).
__global__ __launch_bounds__(512) void kStep(
    const float* __restrict__ wih_b, const float* __restrict__ b_ih,
    const float* __restrict__ whh_a, const float* __restrict__ whh_b,
    const float* __restrict__ b_hh,
    float* __restrict__ out, int t,
    float* __restrict__ hdst, float* __restrict__ cdst) {

    __shared__ __align__(16) float vs[NB * RV];        // [bb][40] combined v
    __shared__ __align__(16) float wast[RNK * WTS];    // whh_a tile, transposed [r][jj]
    __shared__ __align__(16) float cs[NB * 128];       // c tile
    __shared__ __align__(16) float sg[512];            // gate exchange
    __shared__ __align__(16) float hs[128];            // new h of current row
    __shared__ __align__(16) float partsh[16 * 33];    // hu reduction

    const int tid  = threadIdx.x;
    const int gate = tid >> 7, jj = tid & 127;
    const int jt = blockIdx.x, bc = blockIdx.y;
    const int j0 = jt * 128, b0 = bc * NB;
    const int j = j0 + jj, col = gate * 512 + j;

    // weights: rows 0-19 = wih_b, 20-39 = whh_b (column `col`)
    float wreg[RV];
#pragma unroll
    for (int r = 0; r < RNK; r++) wreg[r]       = wih_b[r * G4 + col];
#pragma unroll
    for (int r = 0; r < RNK; r++) wreg[RNK + r] = whh_b[r * G4 + col];
    const float biasv = b_ih[col] + b_hh[col];

    const float* rd = g_hu[t & 1];
    float*       wr = g_hu[(t + 1) & 1];

    // stage whh_a tile (transposed, padded)
    for (int idx = tid; idx < 128 * RNK; idx += 512) {
        int rx = idx % RNK, jx = idx / RNK;
        wast[rx * WTS + jx] = whh_a[(j0 + jx) * RNK + rx];
    }
    // stage c tile
    for (int idx = tid; idx < NB * 128; idx += 512)
        cs[idx] = g_c[(b0 + (idx >> 7)) * HSZ + j0 + (idx & 127)];
    // stage v = [u_t | sum of 4 hu partials]
    for (int idx = tid; idx < NB * RNK; idx += 512) {
        int bbx = idx / RNK, rx = idx % RNK;
        vs[bbx * RV + rx] = g_u[(b0 + bbx) * (TSEQ * RNK) + t * RNK + rx];
        int bi = (b0 + bbx) * RNK + rx;
        vs[bbx * RV + RNK + rx] = rd[bi] + rd[BATCH * RNK + bi]
                                + rd[2 * BATCH * RNK + bi] + rd[3 * BATCH * RNK + bi];
    }
    __syncthreads();

    const int rr = tid & 31, seg = tid >> 5;

    for (int bb = 0; bb < NB; ++bb) {
        // ---- gate GEMV: 40 FMA / thread, v via broadcast LDS.128 ----
        const float4* v4 = reinterpret_cast<const float4*>(vs + bb * RV);
        float a0 = biasv, a1 = 0.f;
#pragma unroll
        for (int q = 0; q < 10; q += 2) {
            float4 va = v4[q], vb = v4[q + 1];
            a0 = fmaf(va.x, wreg[4*q+0], a0); a0 = fmaf(va.y, wreg[4*q+1], a0);
            a0 = fmaf(va.z, wreg[4*q+2], a0); a0 = fmaf(va.w, wreg[4*q+3], a0);
            a1 = fmaf(vb.x, wreg[4*q+4], a1); a1 = fmaf(vb.y, wreg[4*q+5], a1);
            a1 = fmaf(vb.z, wreg[4*q+6], a1); a1 = fmaf(vb.w, wreg[4*q+7], a1);
        }
        float acc = a0 + a1;
        float act = (gate == 2) ? tanhf(acc) : 1.f / (1.f + __expf(-acc));
        sg[tid] = act;
        __syncthreads();

        // ---- cell update (warps 0-3) ----
        if (gate == 0) {
            float ig = sg[jj], fg = sg[128 + jj], gg = sg[256 + jj], og = sg[384 + jj];
            float cc = fmaf(fg, cs[bb * 128 + jj], ig * gg);
            float hh = og * tanhf(cc);
            int b = b0 + bb;
            g_c[b * HSZ + j] = cc;
            out[(b * TSEQ + t) * HSZ + j] = hh;
            if (hdst) { hdst[b * HSZ + j] = hh; cdst[b * HSZ + j] = cc; }
            hs[jj] = hh;
        }
        __syncthreads();

        // ---- fused hu partial for next step: part[r] += h[jj]*whh_a[jj][r] ----
        {
            const float4* h4 = reinterpret_cast<const float4*>(hs + seg * 8);
            float4 ha = h4[0], hb = h4[1];
            float part = 0.f;
            if (rr < RNK) {
                const float4* w4 = reinterpret_cast<const float4*>(wast + rr * WTS + seg * 8);
                float4 w0 = w4[0], w1 = w4[1];
                part = ha.x*w0.x + ha.y*w0.y + ha.z*w0.z + ha.w*w0.w
                     + hb.x*w1.x + hb.y*w1.y + hb.z*w1.z + hb.w*w1.w;
            }
            partsh[seg * 33 + rr] = part;
        }
        __syncthreads();
        if (tid < RNK) {
            float s = 0.f;
#pragma unroll
            for (int sm = 0; sm < 16; sm++) s += partsh[sm * 33 + tid];
            wr[(jt * BATCH + b0 + bb) * RNK + tid] = s;
        }
    }
}

// ---------------------------------------------------------------------------
extern "C" void kernel_launch(void* const* d_in, const int* in_sizes, int n_in,
                              void* d_out, int out_size) {
    const float* x     = (const float*)d_in[0];
    const float* wih_a = (const float*)d_in[1];
    const float* wih_b = (const float*)d_in[2];
    const float* b_ih  = (const float*)d_in[3];
    const float* whh_a = (const float*)d_in[4];
    const float* whh_b = (const float*)d_in[5];
    const float* b_hh  = (const float*)d_in[6];
    float* out = (float*)d_out;

    const long BTH = (long)BATCH * TSEQ * HSZ;
    float* hdst = nullptr;
    float* cdst = nullptr;
    if ((long)out_size >= BTH + 2L * BATCH * HSZ) {
        hdst = out + BTH;
        cdst = hdst + (long)BATCH * HSZ;
    }

    kInit<<<512, 512>>>();
    kPre<<<(BATCH * TSEQ) / 256, 256>>>(x, wih_a);
    for (int t = 0; t < TSEQ; t++) {
        bool last = (t == TSEQ - 1);
        kStep<<<dim3(4, 128), 512>>>(wih_b, b_ih, whh_a, whh_b, b_hh, out, t,
                                     last ? hdst : nullptr, last ? cdst : nullptr);
    }
}

// round 2
// speedup vs baseline: 1.7746x; 1.7746x over previous
#include <cuda_runtime.h>

#define BATCH 4096
#define TSEQ  20
#define INSZ  512
#define HSZ   512
#define RNK   20
#define G4    2048
#define NB    64          // batch rows per block
#define JT    128         // j columns per block
#define WSTR  164         // ws row stride (floats): 4-way STS conflict, 16B-aligned reads
#define HSTR  129         // ht row stride (odd -> conflict-free lane reads)

// Scratch (no allocations allowed -> device globals)
__device__ float g_u[BATCH * TSEQ * RNK];      // [b][t][r] input projection
__device__ float g_c[BATCH * HSZ];             // cell state, tiled [(bc*4+jt)][jjl*64+bb]
__device__ float g_hu[2][4 * BATCH * RNK];     // [parity][jt][b][r] h@whh_a partials

typedef unsigned long long ull;

__device__ __forceinline__ void ffma2(ull &d, ull a, ull b) {
    asm("fma.rn.f32x2 %0, %1, %2, %0;" : "+l"(d) : "l"(a), "l"(b));
}
__device__ __forceinline__ ull pack2(float x, float y) {
    ull r; asm("mov.b64 %0, {%1, %2};" : "=l"(r) : "f"(x), "f"(y)); return r;
}
__device__ __forceinline__ float2 unpack2(ull v) {
    float2 f; asm("mov.b64 {%0, %1}, %2;" : "=f"(f.x), "=f"(f.y) : "l"(v)); return f;
}
__device__ __forceinline__ float sigf(float x) {
    return __fdividef(1.0f, 1.0f + __expf(-x));
}
__device__ __forceinline__ float tanhfast(float x) {
    float e = __expf(-2.0f * fabsf(x));                // e in (0,1]
    float t = __fdividef(1.0f - e, 1.0f + e);
    return copysignf(t, x);
}

// ---------------------------------------------------------------------------
__global__ void kInit() {
    const int n1 = BATCH * HSZ;
    const int n2 = 4 * BATCH * RNK;
    const int stride = gridDim.x * blockDim.x;
    for (int i = blockIdx.x * blockDim.x + threadIdx.x; i < n1; i += stride) g_c[i] = 0.f;
    for (int i = blockIdx.x * blockDim.x + threadIdx.x; i < n2; i += stride) g_hu[0][i] = 0.f;
}

// ---------------------------------------------------------------------------
// u[m][r] = sum_k x[m][k] * wih_a[k][r]
__global__ __launch_bounds__(256) void kPre(const float* __restrict__ x,
                                            const float* __restrict__ wa) {
    __shared__ __align__(16) float was[INSZ * RNK];
    for (int idx = threadIdx.x; idx < INSZ * RNK; idx += blockDim.x) was[idx] = wa[idx];
    __syncthreads();

    const int row = blockIdx.x * blockDim.x + threadIdx.x;
    const float4* xr = reinterpret_cast<const float4*>(x + (long)row * INSZ);

    float acc[RNK];
#pragma unroll
    for (int r = 0; r < RNK; r++) acc[r] = 0.f;

#pragma unroll 4
    for (int k4 = 0; k4 < INSZ / 4; k4++) {
        float4 xv = xr[k4];
#pragma unroll
        for (int i = 0; i < 4; i++) {
            float kv = (i == 0) ? xv.x : (i == 1) ? xv.y : (i == 2) ? xv.z : xv.w;
            const float4* w4 = reinterpret_cast<const float4*>(was + (k4 * 4 + i) * RNK);
#pragma unroll
            for (int q = 0; q < 5; q++) {
                float4 w = w4[q];
                acc[4*q+0] = fmaf(kv, w.x, acc[4*q+0]);
                acc[4*q+1] = fmaf(kv, w.y, acc[4*q+1]);
                acc[4*q+2] = fmaf(kv, w.z, acc[4*q+2]);
                acc[4*q+3] = fmaf(kv, w.w, acc[4*q+3]);
            }
        }
    }
    float* up = g_u + (long)row * RNK;
#pragma unroll
    for (int r = 0; r < RNK; r++) up[r] = acc[r];
}

// ---------------------------------------------------------------------------
// smem partition (floats)
#define WS_OFF   0
#define WS_SZ    (JT * WSTR)          // 20992
#define WAST_OFF (WS_OFF + WS_SZ)
#define WAST_SZ  (JT * RNK)           // 2560
#define VS_OFF   (WAST_OFF + WAST_SZ)
#define VS_SZ    (NB * 40)            // 2560
#define CS_OFF   (VS_OFF + VS_SZ)
#define CS_SZ    (JT * NB)            // 8192
#define HT_OFF   (CS_OFF + CS_SZ)
#define HT_SZ    (NB * HSTR)          // 8256
#define BS_OFF   (HT_OFF + HT_SZ)
#define BS_SZ    512
#define SMEM_FLOATS (BS_OFF + BS_SZ)  // 43072 floats = 172288 B

__global__ __launch_bounds__(512, 1) void kStep(
    const float* __restrict__ wih_b, const float* __restrict__ b_ih,
    const float* __restrict__ whh_a, const float* __restrict__ whh_b,
    const float* __restrict__ b_hh,
    float* __restrict__ out, int t,
    float* __restrict__ hdst, float* __restrict__ cdst) {

    extern __shared__ __align__(16) float sm[];
    float* ws   = sm + WS_OFF;
    float* wast = sm + WAST_OFF;
    float* vs   = sm + VS_OFF;
    float* cs   = sm + CS_OFF;
    float* ht   = sm + HT_OFF;
    float* bs   = sm + BS_OFF;

    const int tid = threadIdx.x;
    const int w   = tid >> 5, l = tid & 31;
    const int jt  = blockIdx.x, bc = blockIdx.y;
    const int j0  = jt * JT, b0 = bc * NB;
    const int ctile = (bc * 4 + jt) * (JT * NB);

    const float* rd = g_hu[t & 1];
    float*       wr = g_hu[(t + 1) & 1];

    // ---- stage weights ws[jjl*WSTR + gate*40 + r] (coalesced LDG, 4-way STS) ----
    {
        int jjl = tid & 127;
        int rb  = tid >> 7;  // 0..3
#pragma unroll
        for (int it = 0; it < 40; it++) {
            int rid  = it * 4 + rb;          // 0..159 = gate*40 + r
            int gate = rid / 40, r = rid % 40;
            int col  = gate * 512 + j0 + jjl;
            float wv = (r < RNK) ? wih_b[r * G4 + col] : whh_b[(r - RNK) * G4 + col];
            ws[jjl * WSTR + rid] = wv;
        }
    }
    // ---- bias ----
    {
        int gate = tid >> 7, jjl = tid & 127;
        int col = gate * 512 + j0 + jjl;
        bs[tid] = b_ih[col] + b_hh[col];
    }
    // ---- wast = whh_a tile (straight copy) ----
    for (int idx = tid; idx < JT * RNK; idx += 512)
        wast[idx] = whh_a[j0 * RNK + idx];
    // ---- c tile ----
    for (int idx = tid; idx < JT * NB; idx += 512)
        cs[idx] = g_c[ctile + idx];
    // ---- v = [u_t | sum of 4 hu partials], layout vs[r*64 + bb] ----
    for (int idx = tid; idx < NB * 40; idx += 512) {
        int bb = idx / 40, r = idx % 40;
        int b  = b0 + bb;
        float v;
        if (r < RNK) {
            v = g_u[b * (TSEQ * RNK) + t * RNK + r];
        } else {
            int off = b * RNK + (r - RNK);
            v = rd[off] + rd[BATCH * RNK + off]
              + rd[2 * BATCH * RNK + off] + rd[3 * BATCH * RNK + off];
        }
        vs[r * NB + bb] = v;
    }
    __syncthreads();

    // ---- pack v into f32x2 registers: 2 rows per thread (bb = l, l+32) ----
    ull vp0[20], vp1[20];
#pragma unroll
    for (int q = 0; q < 20; q++) {
        vp0[q] = pack2(vs[(2 * q) * NB + l],      vs[(2 * q + 1) * NB + l]);
        vp1[q] = pack2(vs[(2 * q) * NB + l + 32], vs[(2 * q + 1) * NB + l + 32]);
    }

    const bool last = (hdst != nullptr);

    // ---- gate + cell loop: warp w owns jjl = w*8 .. w*8+7 ----
#pragma unroll
    for (int q8 = 0; q8 < 8; q8++) {
        const int jjl = w * 8 + q8;
        const ulonglong2* wq = reinterpret_cast<const ulonglong2*>(ws + jjl * WSTR);

        ull acc[4][2];
#pragma unroll
        for (int g = 0; g < 4; g++) { acc[g][0] = 0ull; acc[g][1] = 0ull; }

#pragma unroll
        for (int q = 0; q < 10; q++) {
#pragma unroll
            for (int g = 0; g < 4; g++) {
                ulonglong2 wv = wq[g * 10 + q];       // 4 weights = 2 pairs (broadcast)
                ffma2(acc[g][0], vp0[2 * q],     wv.x);
                ffma2(acc[g][0], vp0[2 * q + 1], wv.y);
                ffma2(acc[g][1], vp1[2 * q],     wv.x);
                ffma2(acc[g][1], vp1[2 * q + 1], wv.y);
            }
        }

        float bi = bs[0 * 128 + jjl], bf = bs[1 * 128 + jjl];
        float bg = bs[2 * 128 + jjl], bo = bs[3 * 128 + jjl];

#pragma unroll
        for (int row = 0; row < 2; row++) {
            int bb = l + row * 32;
            float2 si = unpack2(acc[0][row]);
            float2 sf = unpack2(acc[1][row]);
            float2 sg2 = unpack2(acc[2][row]);
            float2 so = unpack2(acc[3][row]);
            float gi = sigf(si.x + si.y + bi);
            float gf = sigf(sf.x + sf.y + bf);
            float gg = tanhfast(sg2.x + sg2.y + bg);
            float go = sigf(so.x + so.y + bo);

            float cold = cs[jjl * NB + bb];
            float cc = fmaf(gf, cold, gi * gg);
            float hh = go * tanhfast(cc);

            g_c[ctile + jjl * NB + bb] = cc;
            cs[jjl * NB + bb] = cc;            // in-place (only this thread touches slot)
            ht[bb * HSTR + jjl] = hh;
        }
    }
    __syncthreads();

    // ---- coalesced output writes: 4 rows per warp ----
#pragma unroll
    for (int rr = 0; rr < 4; rr++) {
        int bb = w * 4 + rr;
        int b  = b0 + bb;
        float4 hv;
        hv.x = ht[bb * HSTR + 4 * l + 0];
        hv.y = ht[bb * HSTR + 4 * l + 1];
        hv.z = ht[bb * HSTR + 4 * l + 2];
        hv.w = ht[bb * HSTR + 4 * l + 3];
        reinterpret_cast<float4*>(out + ((long)b * TSEQ + t) * HSZ + j0)[l] = hv;
        if (last) {
            reinterpret_cast<float4*>(hdst + (long)b * HSZ + j0)[l] = hv;
            float4 cv;
            cv.x = cs[(4 * l + 0) * NB + bb];
            cv.y = cs[(4 * l + 1) * NB + bb];
            cv.z = cs[(4 * l + 2) * NB + bb];
            cv.w = cs[(4 * l + 3) * NB + bb];
            reinterpret_cast<float4*>(cdst + (long)b * HSZ + j0)[l] = cv;
        }
    }

    // ---- fused hu partials for next step: hu[bb][r] = sum_j h[bb][j]*whh_a[j0+j][r] ----
    for (int o = tid; o < NB * RNK; o += 512) {
        int r = o >> 6, bb = o & 63;
        const float* hrow = ht + bb * HSTR;
        float a0 = 0.f, a1 = 0.f, a2 = 0.f, a3 = 0.f;
#pragma unroll
        for (int j = 0; j < JT; j += 4) {
            a0 = fmaf(hrow[j + 0], wast[(j + 0) * RNK + r], a0);
            a1 = fmaf(hrow[j + 1], wast[(j + 1) * RNK + r], a1);
            a2 = fmaf(hrow[j + 2], wast[(j + 2) * RNK + r], a2);
            a3 = fmaf(hrow[j + 3], wast[(j + 3) * RNK + r], a3);
        }
        wr[jt * (BATCH * RNK) + (b0 + bb) * RNK + r] = (a0 + a1) + (a2 + a3);
    }
}

// ---------------------------------------------------------------------------
extern "C" void kernel_launch(void* const* d_in, const int* in_sizes, int n_in,
                              void* d_out, int out_size) {
    const float* x     = (const float*)d_in[0];
    const float* wih_a = (const float*)d_in[1];
    const float* wih_b = (const float*)d_in[2];
    const float* b_ih  = (const float*)d_in[3];
    const float* whh_a = (const float*)d_in[4];
    const float* whh_b = (const float*)d_in[5];
    const float* b_hh  = (const float*)d_in[6];
    float* out = (float*)d_out;

    const long BTH = (long)BATCH * TSEQ * HSZ;
    float* hdst = nullptr;
    float* cdst = nullptr;
    if ((long)out_size >= BTH + 2L * BATCH * HSZ) {
        hdst = out + BTH;
        cdst = hdst + (long)BATCH * HSZ;
    }

    static_assert(SMEM_FLOATS * 4 == 172288, "smem layout");
    cudaFuncSetAttribute(kStep, cudaFuncAttributeMaxDynamicSharedMemorySize,
                         SMEM_FLOATS * 4);

    kInit<<<512, 512>>>();
    kPre<<<(BATCH * TSEQ) / 256, 256>>>(x, wih_a);
    for (int t = 0; t < TSEQ; t++) {
        bool lastT = (t == TSEQ - 1);
        kStep<<<dim3(4, 64), 512, SMEM_FLOATS * 4>>>(
            wih_b, b_ih, whh_a, whh_b, b_hh, out, t,
            lastT ? hdst : nullptr, lastT ? cdst : nullptr);
    }
}

// round 3
// speedup vs baseline: 2.2876x; 1.2891x over previous
#include <cuda_runtime.h>

#define BATCH 4096
#define TSEQ  20
#define INSZ  512
#define HSZ   512
#define RNK   20
#define G4    2048
#define NB    64          // batch rows per block
#define JT    128         // j columns per block
#define HSTRD 132         // ht/wa row stride (33*16B -> conflict-free, 16B aligned)

// Scratch (no allocations allowed -> device globals)
__device__ float g_u[BATCH * TSEQ * RNK];      // [b][t][r] input projection
__device__ float g_c[BATCH * HSZ];             // cell state, tiled [(bc*4+jt)][bb][jjl]
__device__ float g_hu[2][4 * BATCH * RNK];     // [parity][jt][b][r] h@whh_a partials

typedef unsigned long long ull;

__device__ __forceinline__ void ffma2(ull &d, ull a, ull b) {
    asm("fma.rn.f32x2 %0, %1, %2, %0;" : "+l"(d) : "l"(a), "l"(b));
}
__device__ __forceinline__ ull pack2(float x, float y) {
    ull r; asm("mov.b64 %0, {%1, %2};" : "=l"(r) : "f"(x), "f"(y)); return r;
}
__device__ __forceinline__ float2 unpack2(ull v) {
    float2 f; asm("mov.b64 {%0, %1}, %2;" : "=f"(f.x), "=f"(f.y) : "l"(v)); return f;
}
__device__ __forceinline__ float sigf(float x) {
    return __fdividef(1.0f, 1.0f + __expf(-x));
}
__device__ __forceinline__ float tanhfast(float x) {
    float e = __expf(-2.0f * fabsf(x));
    float t = __fdividef(1.0f - e, 1.0f + e);
    return copysignf(t, x);
}

// ---------------------------------------------------------------------------
__global__ void kInit() {
    const int n1 = BATCH * HSZ;
    const int n2 = 4 * BATCH * RNK;
    const int stride = gridDim.x * blockDim.x;
    for (int i = blockIdx.x * blockDim.x + threadIdx.x; i < n1; i += stride) g_c[i] = 0.f;
    for (int i = blockIdx.x * blockDim.x + threadIdx.x; i < n2; i += stride) g_hu[0][i] = 0.f;
}

// ---------------------------------------------------------------------------
// u[m][r] = sum_k x[m][k] * wih_a[k][r], f32x2 over rank pairs
__global__ __launch_bounds__(256) void kPre(const float* __restrict__ x,
                                            const float* __restrict__ wa) {
    __shared__ __align__(16) float was[INSZ * RNK];
    for (int idx = threadIdx.x; idx < INSZ * RNK; idx += blockDim.x) was[idx] = wa[idx];
    __syncthreads();

    const int row = blockIdx.x * blockDim.x + threadIdx.x;
    const float4* xr = reinterpret_cast<const float4*>(x + (long)row * INSZ);

    ull acc[10];
#pragma unroll
    for (int q = 0; q < 10; q++) acc[q] = 0ull;

#pragma unroll 4
    for (int k4 = 0; k4 < INSZ / 4; k4++) {
        float4 xv = xr[k4];
#pragma unroll
        for (int i = 0; i < 4; i++) {
            float kv = (i == 0) ? xv.x : (i == 1) ? xv.y : (i == 2) ? xv.z : xv.w;
            ull ks = pack2(kv, kv);
            const ulonglong2* w2 = reinterpret_cast<const ulonglong2*>(was + (k4 * 4 + i) * RNK);
#pragma unroll
            for (int q = 0; q < 5; q++) {
                ulonglong2 wv = w2[q];
                ffma2(acc[2 * q + 0], ks, wv.x);
                ffma2(acc[2 * q + 1], ks, wv.y);
            }
        }
    }
    float* up = g_u + (long)row * RNK;
#pragma unroll
    for (int q = 0; q < 10; q++) {
        float2 f = unpack2(acc[q]);
        up[2 * q + 0] = f.x;
        up[2 * q + 1] = f.y;
    }
}

// ---------------------------------------------------------------------------
// smem partition (floats)
#define WT_OFF   0
#define WT_SZ    (40 * 512)                 // 20480  wT[k][m], m = jjl*4+gate
#define VS_OFF   (WT_OFF + WT_SZ)
#define VS_SZ    (40 * NB * 2)              // 5120   vsplat[k][bb] as ull
#define BS_OFF   (VS_OFF + VS_SZ)
#define BS_SZ    512
#define HT_OFF   (BS_OFF + BS_SZ)
#define HT_SZ    (NB * HSTRD)               // 8448
#define WA_OFF   (HT_OFF + HT_SZ)
#define WA_SZ    (RNK * HSTRD)              // 2640
#define SMEM_FLOATS (WA_OFF + WA_SZ)        // 37200 floats = 148800 B

__global__ __launch_bounds__(512, 1) void kStep(
    const float* __restrict__ wih_b, const float* __restrict__ b_ih,
    const float* __restrict__ whh_a, const float* __restrict__ whh_b,
    const float* __restrict__ b_hh,
    float* __restrict__ out, int t,
    float* __restrict__ hdst, float* __restrict__ cdst) {

    extern __shared__ __align__(16) float sm[];
    float* wT = sm + WT_OFF;
    ull*   vsp = reinterpret_cast<ull*>(sm + VS_OFF);
    float* bs = sm + BS_OFF;
    float* ht = sm + HT_OFF;
    float* wa = sm + WA_OFF;

    const int tid = threadIdx.x;
    const int jt = blockIdx.x, bc = blockIdx.y;
    const int j0 = jt * JT, b0 = bc * NB;
    const int mtile = tid & 63, ntile = tid >> 6;     // 64 x 8 thread grid
    const int m0 = mtile * 8, jjl0 = mtile * 2, bb0 = ntile * 8;
    const long ctile = (long)(bc * 4 + jt) * (NB * JT);

    const float* rd = g_hu[t & 1];
    float*       wr = g_hu[(t + 1) & 1];

    // ---- prefetch this thread's c cells early (LDG, hidden behind staging) ----
    float2 creg[8];
#pragma unroll
    for (int n = 0; n < 8; n++)
        creg[n] = *reinterpret_cast<const float2*>(g_c + ctile + (bb0 + n) * JT + jjl0);

    // ---- stage wT[k][jjl*4+gate] (coalesced LDG per 128-col chunk) ----
#pragma unroll
    for (int it = 0; it < 40; it++) {
        int idx = it * 512 + tid;
        int jjl = idx & 127, gate = (idx >> 7) & 3, r = idx >> 9;
        float wv = (r < RNK) ? wih_b[r * G4 + gate * 512 + j0 + jjl]
                             : whh_b[(r - RNK) * G4 + gate * 512 + j0 + jjl];
        wT[r * 512 + jjl * 4 + gate] = wv;
    }
    // ---- bias in m-order ----
    {
        int jjl = tid >> 2, gate = tid & 3;
        int col = gate * 512 + j0 + jjl;
        bs[tid] = b_ih[col] + b_hh[col];
    }
    // ---- wa[r][j] = whh_a[j0+j][r] (transposed, coalesced LDG) ----
    for (int idx = tid; idx < JT * RNK; idx += 512) {
        int r = idx % RNK, j = idx / RNK;
        wa[r * HSTRD + j] = whh_a[(j0 + j) * RNK + r];
    }
    // ---- v = [u_t | sum of 4 hu partials], stored pre-splatted ----
    for (int idx = tid; idx < NB * 40; idx += 512) {
        int bb = idx / 40, r = idx % 40;
        int b = b0 + bb;
        float v;
        if (r < RNK) {
            v = g_u[b * (TSEQ * RNK) + t * RNK + r];
        } else {
            int off = b * RNK + (r - RNK);
            v = rd[off] + rd[BATCH * RNK + off]
              + rd[2 * BATCH * RNK + off] + rd[3 * BATCH * RNK + off];
        }
        vsp[r * NB + bb] = pack2(v, v);
    }
    __syncthreads();

    // ---- main GEMM: acc[mp][n], mp = m-pair (f32x2), n = bb ----
    ull acc[4][8];
#pragma unroll
    for (int mp = 0; mp < 4; mp++)
#pragma unroll
        for (int n = 0; n < 8; n++) acc[mp][n] = 0ull;

#pragma unroll 8
    for (int k = 0; k < 40; k++) {
        const ulonglong2* wrow = reinterpret_cast<const ulonglong2*>(wT + k * 512 + m0);
        ulonglong2 wA = wrow[0], wB = wrow[1];
        const ulonglong2* vrow = reinterpret_cast<const ulonglong2*>(vsp + k * NB + bb0);
        ulonglong2 v0 = vrow[0], v1 = vrow[1], v2 = vrow[2], v3 = vrow[3];
        ull wp[4] = {wA.x, wA.y, wB.x, wB.y};
        ull vn[8] = {v0.x, v0.y, v1.x, v1.y, v2.x, v2.y, v3.x, v3.y};
#pragma unroll
        for (int mp = 0; mp < 4; mp++)
#pragma unroll
            for (int n = 0; n < 8; n++)
                ffma2(acc[mp][n], wp[mp], vn[n]);
    }

    // ---- epilogue: full cell update in-thread ----
    const float4 bA = *reinterpret_cast<const float4*>(bs + m0);      // jjl0: i f g o
    const float4 bB = *reinterpret_cast<const float4*>(bs + m0 + 4);  // jjl0+1
    const bool last = (hdst != nullptr);

#pragma unroll
    for (int n = 0; n < 8; n++) {
        int bb = bb0 + n;
        int b = b0 + bb;
        float2 cold = creg[n];
        float2 cc, hh;
#pragma unroll
        for (int jp = 0; jp < 2; jp++) {
            float2 sif = unpack2(acc[2 * jp + 0][n]);
            float2 sgo = unpack2(acc[2 * jp + 1][n]);
            float bi = jp ? bB.x : bA.x, bf = jp ? bB.y : bA.y;
            float bg = jp ? bB.z : bA.z, bo = jp ? bB.w : bA.w;
            float gi = sigf(sif.x + bi);
            float gf = sigf(sif.y + bf);
            float gg = tanhfast(sgo.x + bg);
            float go = sigf(sgo.y + bo);
            float co = jp ? cold.y : cold.x;
            float cn = fmaf(gf, co, gi * gg);
            float hn = go * tanhfast(cn);
            if (jp) { cc.y = cn; hh.y = hn; } else { cc.x = cn; hh.x = hn; }
        }
        *reinterpret_cast<float2*>(g_c + ctile + bb * JT + jjl0) = cc;
        *reinterpret_cast<float2*>(out + ((long)b * TSEQ + t) * HSZ + j0 + jjl0) = hh;
        *reinterpret_cast<float2*>(ht + bb * HSTRD + jjl0) = hh;
        if (last) {
            *reinterpret_cast<float2*>(hdst + (long)b * HSZ + j0 + jjl0) = hh;
            *reinterpret_cast<float2*>(cdst + (long)b * HSZ + j0 + jjl0) = cc;
        }
    }
    __syncthreads();

    // ---- hu partials for next step: hu[bb][r] = sum_j h[bb][j]*wa[r][j] ----
    for (int o = tid; o < NB * RNK; o += 512) {
        int r = o >> 6, bb = o & 63;
        const ulonglong2* hp = reinterpret_cast<const ulonglong2*>(ht + bb * HSTRD);
        const ulonglong2* wp = reinterpret_cast<const ulonglong2*>(wa + r * HSTRD);
        ull a0 = 0ull, a1 = 0ull;
#pragma unroll
        for (int q = 0; q < JT / 4; q++) {
            ulonglong2 hv = hp[q];
            ulonglong2 wv = wp[q];
            ffma2(a0, hv.x, wv.x);
            ffma2(a1, hv.y, wv.y);
        }
        float2 f0 = unpack2(a0), f1 = unpack2(a1);
        wr[jt * (BATCH * RNK) + (b0 + bb) * RNK + r] = (f0.x + f0.y) + (f1.x + f1.y);
    }
}

// ---------------------------------------------------------------------------
extern "C" void kernel_launch(void* const* d_in, const int* in_sizes, int n_in,
                              void* d_out, int out_size) {
    const float* x     = (const float*)d_in[0];
    const float* wih_a = (const float*)d_in[1];
    const float* wih_b = (const float*)d_in[2];
    const float* b_ih  = (const float*)d_in[3];
    const float* whh_a = (const float*)d_in[4];
    const float* whh_b = (const float*)d_in[5];
    const float* b_hh  = (const float*)d_in[6];
    float* out = (float*)d_out;

    const long BTH = (long)BATCH * TSEQ * HSZ;
    float* hdst = nullptr;
    float* cdst = nullptr;
    if ((long)out_size >= BTH + 2L * BATCH * HSZ) {
        hdst = out + BTH;
        cdst = hdst + (long)BATCH * HSZ;
    }

    cudaFuncSetAttribute(kStep, cudaFuncAttributeMaxDynamicSharedMemorySize,
                         SMEM_FLOATS * 4);

    kInit<<<512, 512>>>();
    kPre<<<(BATCH * TSEQ) / 256, 256>>>(x, wih_a);
    for (int t = 0; t < TSEQ; t++) {
        bool lastT = (t == TSEQ - 1);
        kStep<<<dim3(4, 64), 512, SMEM_FLOATS * 4>>>(
            wih_b, b_ih, whh_a, whh_b, b_hh, out, t,
            lastT ? hdst : nullptr, lastT ? cdst : nullptr);
    }
}

// round 4
// speedup vs baseline: 2.8985x; 1.2670x over previous
#include <cuda_runtime.h>

#define BATCH 4096
#define TSEQ  20
#define INSZ  512
#define HSZ   512
#define RNK   20
#define G4    2048
#define NB    64          // batch rows per block
#define JT    128         // j columns per block
#define HSTRD 130         // ht row stride (even -> float2 stores OK, 2-way col conflict)

// Scratch (no allocations allowed -> device globals)
__device__ float g_u[BATCH * TSEQ * RNK];      // [b][t][r] input projection
__device__ float g_c[BATCH * HSZ];             // cell state, tiled [(bc*4+jt)][bb][jjl]
__device__ float g_hu[2][4 * BATCH * RNK];     // [parity][jt][b][r] h@whh_a partials

typedef unsigned long long ull;

__device__ __forceinline__ void ffma2(ull &d, ull a, ull b) {
    asm("fma.rn.f32x2 %0, %1, %2, %0;" : "+l"(d) : "l"(a), "l"(b));
}
__device__ __forceinline__ ull add2(ull a, ull b) {
    ull d; asm("add.rn.f32x2 %0, %1, %2;" : "=l"(d) : "l"(a), "l"(b)); return d;
}
__device__ __forceinline__ ull pack2(float x, float y) {
    ull r; asm("mov.b64 %0, {%1, %2};" : "=l"(r) : "f"(x), "f"(y)); return r;
}
__device__ __forceinline__ float2 unpack2(ull v) {
    float2 f; asm("mov.b64 {%0, %1}, %2;" : "=f"(f.x), "=f"(f.y) : "l"(v)); return f;
}
__device__ __forceinline__ float sigf(float x) {
    return __fdividef(1.0f, 1.0f + __expf(-x));
}
__device__ __forceinline__ float tanhfast(float x) {
    float e = __expf(-2.0f * fabsf(x));
    float t = __fdividef(1.0f - e, 1.0f + e);
    return copysignf(t, x);
}

// ---------------------------------------------------------------------------
__global__ void kInit() {
    const int n1 = BATCH * HSZ;
    const int n2 = 4 * BATCH * RNK;
    const int stride = gridDim.x * blockDim.x;
    for (int i = blockIdx.x * blockDim.x + threadIdx.x; i < n1; i += stride) g_c[i] = 0.f;
    for (int i = blockIdx.x * blockDim.x + threadIdx.x; i < n2; i += stride) g_hu[0][i] = 0.f;
}

// ---------------------------------------------------------------------------
__global__ __launch_bounds__(256) void kPre(const float* __restrict__ x,
                                            const float* __restrict__ wa) {
    __shared__ __align__(16) float was[INSZ * RNK];
    for (int idx = threadIdx.x; idx < INSZ * RNK; idx += blockDim.x) was[idx] = wa[idx];
    __syncthreads();

    const int row = blockIdx.x * blockDim.x + threadIdx.x;
    const float4* xr = reinterpret_cast<const float4*>(x + (long)row * INSZ);

    ull acc[10];
#pragma unroll
    for (int q = 0; q < 10; q++) acc[q] = 0ull;

#pragma unroll 4
    for (int k4 = 0; k4 < INSZ / 4; k4++) {
        float4 xv = xr[k4];
#pragma unroll
        for (int i = 0; i < 4; i++) {
            float kv = (i == 0) ? xv.x : (i == 1) ? xv.y : (i == 2) ? xv.z : xv.w;
            ull ks = pack2(kv, kv);
            const ulonglong2* w2 = reinterpret_cast<const ulonglong2*>(was + (k4 * 4 + i) * RNK);
#pragma unroll
            for (int q = 0; q < 5; q++) {
                ulonglong2 wv = w2[q];
                ffma2(acc[2 * q + 0], ks, wv.x);
                ffma2(acc[2 * q + 1], ks, wv.y);
            }
        }
    }
    float* up = g_u + (long)row * RNK;
#pragma unroll
    for (int q = 0; q < 10; q++) {
        float2 f = unpack2(acc[q]);
        up[2 * q + 0] = f.x;
        up[2 * q + 1] = f.y;
    }
}

// ---------------------------------------------------------------------------
// smem partition (floats)
#define WT_OFF   0
#define WT_SZ    (40 * 512)                 // 20480  wT[k][gate*128+jjl]; reused for hu partials
#define VS_OFF   (WT_OFF + WT_SZ)
#define VS_SZ    (40 * NB * 2)              // 5120   vsplat[k][bb] as ull
#define BS_OFF   (VS_OFF + VS_SZ)
#define BS_SZ    512                        // bias [gate][jjl]
#define HT_OFF   (BS_OFF + BS_SZ)
#define HT_SZ    (NB * HSTRD)               // 8320
#define WA_OFF   (HT_OFF + HT_SZ)
#define WA_SZ    (JT * RNK)                 // 2560   wa[j][r]
#define SMEM_FLOATS (WA_OFF + WA_SZ)        // 36992 floats = 147968 B

__global__ __launch_bounds__(512, 1) void kStep(
    const float* __restrict__ wih_b, const float* __restrict__ b_ih,
    const float* __restrict__ whh_a, const float* __restrict__ whh_b,
    const float* __restrict__ b_hh,
    float* __restrict__ out, int t,
    float* __restrict__ hdst, float* __restrict__ cdst) {

    extern __shared__ __align__(16) float sm[];
    float* wT  = sm + WT_OFF;
    ull*   vsp = reinterpret_cast<ull*>(sm + VS_OFF);
    float* bs  = sm + BS_OFF;
    float* ht  = sm + HT_OFF;
    float* wa  = sm + WA_OFF;

    const int tid = threadIdx.x;
    const int jt = blockIdx.x, bc = blockIdx.y;
    const int j0 = jt * JT, b0 = bc * NB;
    const int mtile = tid & 63, ntile = tid >> 6;     // 64 x 8 thread grid
    const int jjl0 = mtile * 2, bb0 = ntile * 8;
    const long ctile = (long)(bc * 4 + jt) * (NB * JT);

    const float* rd = g_hu[t & 1];
    float*       wr = g_hu[(t + 1) & 1];

    // ---- prefetch this thread's c cells early ----
    float2 creg[8];
#pragma unroll
    for (int n = 0; n < 8; n++)
        creg[n] = *reinterpret_cast<const float2*>(g_c + ctile + (bb0 + n) * JT + jjl0);

    // ---- stage wT[k][gate*128 + jjl] : pure float4 copy, no transpose ----
#pragma unroll
    for (int it = 0; it < 10; it++) {
        int idx4 = it * 512 + tid;          // float4 index in [0, 5120)
        int r = idx4 >> 7;                  // 0..39
        int q = idx4 & 127;                 // float4 within 512-float row
        int gate = q >> 5, jjl4 = q & 31;
        const float* src = (r < RNK) ? (wih_b + r * G4) : (whh_b + (r - RNK) * G4);
        float4 v = reinterpret_cast<const float4*>(src + gate * 512 + j0)[jjl4];
        reinterpret_cast<float4*>(wT + r * 512 + gate * 128)[jjl4] = v;
    }
    // ---- bias [gate][jjl] ----
    {
        int gate = tid >> 7, jjl = tid & 127;
        int col = gate * 512 + j0 + jjl;
        bs[tid] = b_ih[col] + b_hh[col];
    }
    // ---- wa[j][r] = whh_a[(j0+j)][r] : straight float4 copy ----
    for (int idx = tid; idx < (JT * RNK) / 4; idx += 512)
        reinterpret_cast<float4*>(wa)[idx] =
            reinterpret_cast<const float4*>(whh_a + j0 * RNK)[idx];
    // ---- v = [u_t | sum of 4 hu partials], stored pre-splatted ----
    for (int idx = tid; idx < NB * 40; idx += 512) {
        int bb = idx / 40, r = idx % 40;
        int b = b0 + bb;
        float v;
        if (r < RNK) {
            v = g_u[b * (TSEQ * RNK) + t * RNK + r];
        } else {
            int off = b * RNK + (r - RNK);
            v = rd[off] + rd[BATCH * RNK + off]
              + rd[2 * BATCH * RNK + off] + rd[3 * BATCH * RNK + off];
        }
        vsp[r * NB + bb] = pack2(v, v);
    }
    __syncthreads();

    // ---- main GEMM: acc[gate][n] = f32x2 over (jjl0, jjl0+1), bias folded in ----
    ull acc[4][8];
#pragma unroll
    for (int g = 0; g < 4; g++) {
        ull bg = *reinterpret_cast<const ull*>(bs + g * 128 + jjl0);
#pragma unroll
        for (int n = 0; n < 8; n++) acc[g][n] = bg;
    }

#pragma unroll 8
    for (int k = 0; k < 40; k++) {
        ull wg[4];
#pragma unroll
        for (int g = 0; g < 4; g++)
            wg[g] = *reinterpret_cast<const ull*>(wT + k * 512 + g * 128 + jjl0);
        const ulonglong2* vrow = reinterpret_cast<const ulonglong2*>(vsp + k * NB + bb0);
        ulonglong2 v0 = vrow[0], v1 = vrow[1], v2 = vrow[2], v3 = vrow[3];
        ull vn[8] = {v0.x, v0.y, v1.x, v1.y, v2.x, v2.y, v3.x, v3.y};
#pragma unroll
        for (int g = 0; g < 4; g++)
#pragma unroll
            for (int n = 0; n < 8; n++)
                ffma2(acc[g][n], wg[g], vn[n]);
    }

    // ---- epilogue: full cell update in-thread ----
    const bool last = (hdst != nullptr);
#pragma unroll
    for (int n = 0; n < 8; n++) {
        int bb = bb0 + n;
        int b = b0 + bb;
        float2 i2 = unpack2(acc[0][n]);
        float2 f2 = unpack2(acc[1][n]);
        float2 g2 = unpack2(acc[2][n]);
        float2 o2 = unpack2(acc[3][n]);
        float2 cold = creg[n];
        float2 cc, hh;
        cc.x = fmaf(sigf(f2.x), cold.x, sigf(i2.x) * tanhfast(g2.x));
        cc.y = fmaf(sigf(f2.y), cold.y, sigf(i2.y) * tanhfast(g2.y));
        hh.x = sigf(o2.x) * tanhfast(cc.x);
        hh.y = sigf(o2.y) * tanhfast(cc.y);
        *reinterpret_cast<float2*>(g_c + ctile + bb * JT + jjl0) = cc;
        *reinterpret_cast<float2*>(out + ((long)b * TSEQ + t) * HSZ + j0 + jjl0) = hh;
        *reinterpret_cast<float2*>(ht + bb * HSTRD + jjl0) = hh;
        if (last) {
            *reinterpret_cast<float2*>(hdst + (long)b * HSZ + j0 + jjl0) = hh;
            *reinterpret_cast<float2*>(cdst + (long)b * HSZ + j0 + jjl0) = cc;
        }
    }
    __syncthreads();

    // ---- hu partials: thread (js, bb) accumulates ALL 20 r over 16 j ----
    // partial layout (reusing wT region): part[(rp*8+js)*64 + bb] as ull
    {
        ull* part = reinterpret_cast<ull*>(wT);
        const int js = tid >> 6, bb = tid & 63;
        ull a10[10];
#pragma unroll
        for (int rp = 0; rp < 10; rp++) a10[rp] = 0ull;
        const int jbeg = js * 16;
#pragma unroll
        for (int jj = 0; jj < 16; jj++) {
            int j = jbeg + jj;
            float hv = ht[bb * HSTRD + j];
            ull hs2 = pack2(hv, hv);
            const ulonglong2* war = reinterpret_cast<const ulonglong2*>(wa + j * RNK);
            ulonglong2 w0 = war[0], w1 = war[1], w2 = war[2], w3 = war[3], w4 = war[4];
            ffma2(a10[0], hs2, w0.x); ffma2(a10[1], hs2, w0.y);
            ffma2(a10[2], hs2, w1.x); ffma2(a10[3], hs2, w1.y);
            ffma2(a10[4], hs2, w2.x); ffma2(a10[5], hs2, w2.y);
            ffma2(a10[6], hs2, w3.x); ffma2(a10[7], hs2, w3.y);
            ffma2(a10[8], hs2, w4.x); ffma2(a10[9], hs2, w4.y);
        }
#pragma unroll
        for (int rp = 0; rp < 10; rp++)
            part[(rp * 8 + js) * 64 + bb] = a10[rp];
    }
    __syncthreads();

    // ---- reduce 8 jslices, write hu to global ----
    {
        const ull* part = reinterpret_cast<const ull*>(wT);
#pragma unroll
        for (int o = tid; o < NB * 10; o += 512) {
            int bb = o & 63, rp = o >> 6;
            ull s = part[(rp * 8 + 0) * 64 + bb];
#pragma unroll
            for (int js = 1; js < 8; js++)
                s = add2(s, part[(rp * 8 + js) * 64 + bb]);
            float2 f = unpack2(s);
            *reinterpret_cast<float2*>(
                wr + jt * (BATCH * RNK) + (b0 + bb) * RNK + 2 * rp) = f;
        }
    }
}

// ---------------------------------------------------------------------------
extern "C" void kernel_launch(void* const* d_in, const int* in_sizes, int n_in,
                              void* d_out, int out_size) {
    const float* x     = (const float*)d_in[0];
    const float* wih_a = (const float*)d_in[1];
    const float* wih_b = (const float*)d_in[2];
    const float* b_ih  = (const float*)d_in[3];
    const float* whh_a = (const float*)d_in[4];
    const float* whh_b = (const float*)d_in[5];
    const float* b_hh  = (const float*)d_in[6];
    float* out = (float*)d_out;

    const long BTH = (long)BATCH * TSEQ * HSZ;
    float* hdst = nullptr;
    float* cdst = nullptr;
    if ((long)out_size >= BTH + 2L * BATCH * HSZ) {
        hdst = out + BTH;
        cdst = hdst + (long)BATCH * HSZ;
    }

    cudaFuncSetAttribute(kStep, cudaFuncAttributeMaxDynamicSharedMemorySize,
                         SMEM_FLOATS * 4);

    kInit<<<512, 512>>>();
    kPre<<<(BATCH * TSEQ) / 256, 256>>>(x, wih_a);
    for (int t = 0; t < TSEQ; t++) {
        bool lastT = (t == TSEQ - 1);
        kStep<<<dim3(4, 64), 512, SMEM_FLOATS * 4>>>(
            wih_b, b_ih, whh_a, whh_b, b_hh, out, t,
            lastT ? hdst : nullptr, lastT ? cdst : nullptr);
    }
}